// round 7
// baseline (speedup 1.0000x reference)
#include <cuda_runtime.h>
#include <cstdint>

#define NNODES 50000
#define NEDGES 150000
#define EPLUS  (NEDGES + NNODES)   // edges + self loops = 200000
#define NGRAPH 1024
#define INDIM  78
#define HID    640
#define HEADS  10
#define C1     64
#define NEGSLOPE 0.2f
#define INTMIN_ (-2147483647 - 1)

// ---------------- scratch (static __device__ — no allocations allowed) -----
__device__ float g_bufA[(size_t)NNODES * HID];   // xl / xw
__device__ float g_bufB[(size_t)NNODES * HID];   // xr / gcn-acc
__device__ float g_bufC[(size_t)NNODES * HID];   // h / acc
__device__ float g_logits[(size_t)EPLUS * HEADS];
__device__ int   g_mkey[NNODES * HEADS];
__device__ float g_den [NNODES * HEADS];
__device__ float g_deg [NNODES];
__device__ int   g_gmax[NGRAPH * HID];
__device__ float g_gsum[NGRAPH * HID];
__device__ float g_cnt [NGRAPH];

// ---------------- helpers --------------------------------------------------
__device__ __forceinline__ int f2key(float f) {
    int i = __float_as_int(f);
    return i >= 0 ? i : (i ^ 0x7FFFFFFF);
}
__device__ __forceinline__ float key2f(int k) {
    return __int_as_float(k >= 0 ? k : (k ^ 0x7FFFFFFF));
}

// ---------------- fills ----------------------------------------------------
__global__ void k_fill_f(float* p, float v, int n) {
    int i = blockIdx.x * blockDim.x + threadIdx.x;
    if (i < n) p[i] = v;
}
__global__ void k_fill_i(int* p, int v, int n) {
    int i = blockIdx.x * blockDim.x + threadIdx.x;
    if (i < n) p[i] = v;
}

// ---------------- fp32 GEMM, packed f32x2 FMA ------------------------------
// C[M,N] = A[M,K] @ B[K,N], all row-major fp32. Tile 128x128x16, 256 threads,
// 8x8 per thread; inner product via fma.rn.f32x2 (2 FMA/inst — doubles the
// fp32 pipe rate vs what ptxas emits).
#define BM 128
#define BN 128
#define BK 16

__global__ __launch_bounds__(256)
void k_gemm(const float* __restrict__ A, const float* __restrict__ B,
            float* __restrict__ C, int M, int K, int N)
{
    __shared__ float As[BK][BM + 4];   // row stride 132 floats (16B-aligned)
    __shared__ float Bs[BK][BN + 4];

    const int bm  = blockIdx.y * BM;
    const int bn  = blockIdx.x * BN;
    const int tid = threadIdx.x;
    const int tm  = tid >> 4;    // 0..15
    const int tn  = tid & 15;    // 0..15

    unsigned long long acc[8][4];
    #pragma unroll
    for (int i = 0; i < 8; i++)
        #pragma unroll
        for (int j = 0; j < 4; j++) acc[i][j] = 0ull;

    for (int k0 = 0; k0 < K; k0 += BK) {
        // A tile (128x16) -> transposed As[k][m]
        #pragma unroll
        for (int i = 0; i < 8; i++) {
            int r = (tid >> 4) + i * 16;   // 0..127
            int c = tid & 15;              // 0..15
            int gr = bm + r, gc = k0 + c;
            As[c][r] = (gr < M && gc < K) ? A[(size_t)gr * K + gc] : 0.f;
        }
        // B tile (16x128)
        #pragma unroll
        for (int i = 0; i < 8; i++) {
            int r = (tid >> 7) + i * 2;    // 0..15
            int c = tid & 127;             // 0..127
            int gr = k0 + r, gc = bn + c;
            Bs[r][c] = (gr < K && gc < N) ? B[(size_t)gr * N + gc] : 0.f;
        }
        __syncthreads();

        #pragma unroll
        for (int kk = 0; kk < BK; kk++) {
            float4 a0 = *(const float4*)&As[kk][tm * 8];
            float4 a1 = *(const float4*)&As[kk][tm * 8 + 4];
            ulonglong2 bq0 = *(const ulonglong2*)&Bs[kk][tn * 8];
            ulonglong2 bq1 = *(const ulonglong2*)&Bs[kk][tn * 8 + 4];
            float av[8] = {a0.x, a0.y, a0.z, a0.w, a1.x, a1.y, a1.z, a1.w};
            unsigned long long bv[4] = {bq0.x, bq0.y, bq1.x, bq1.y};
            #pragma unroll
            for (int i = 0; i < 8; i++) {
                unsigned long long ad;
                unsigned int ab = __float_as_uint(av[i]);
                asm("mov.b64 %0, {%1, %1};" : "=l"(ad) : "r"(ab));
                #pragma unroll
                for (int j = 0; j < 4; j++) {
                    asm("fma.rn.f32x2 %0, %1, %2, %0;"
                        : "+l"(acc[i][j]) : "l"(ad), "l"(bv[j]));
                }
            }
        }
        __syncthreads();
    }

    #pragma unroll
    for (int i = 0; i < 8; i++) {
        int gr = bm + tm * 8 + i;
        if (gr >= M) continue;
        #pragma unroll
        for (int j = 0; j < 4; j++) {
            int gc = bn + tn * 8 + 2 * j;
            if (gc < N)
                *(float2*)&C[(size_t)gr * N + gc] = *(float2*)&acc[i][j];
        }
    }
}

// ---------------- GATv2 edge pass A: logits + scatter max ------------------
// one warp per edge; H*Ch == HID; Ch % 4 == 0
__global__ void k_edge_logits(const float* __restrict__ xl,
                              const float* __restrict__ xr,
                              const int* __restrict__ ei,
                              const float* __restrict__ att,
                              float* __restrict__ logits,
                              int* __restrict__ mkey,
                              int H, int Ch)
{
    int e = (blockIdx.x * blockDim.x + threadIdx.x) >> 5;
    int lane = threadIdx.x & 31;
    if (e >= EPLUS) return;
    int s, d;
    if (e < NEDGES) { s = ei[e]; d = ei[NEDGES + e]; }
    else            { s = d = e - NEDGES; }
    const float4* pl = (const float4*)(xl + (size_t)s * HID);
    const float4* pr = (const float4*)(xr + (size_t)d * HID);
    const float4* pa = (const float4*)att;
    int Q = Ch >> 2;                         // float4s per head
    for (int h = 0; h < H; h++) {
        float sum = 0.f;
        for (int q = lane; q < Q; q += 32) {
            float4 l4 = pl[h * Q + q];
            float4 r4 = pr[h * Q + q];
            float4 a4 = pa[h * Q + q];
            float v;
            v = l4.x + r4.x; v = v > 0.f ? v : NEGSLOPE * v; sum += v * a4.x;
            v = l4.y + r4.y; v = v > 0.f ? v : NEGSLOPE * v; sum += v * a4.y;
            v = l4.z + r4.z; v = v > 0.f ? v : NEGSLOPE * v; sum += v * a4.z;
            v = l4.w + r4.w; v = v > 0.f ? v : NEGSLOPE * v; sum += v * a4.w;
        }
        #pragma unroll
        for (int o = 16; o > 0; o >>= 1)
            sum += __shfl_xor_sync(0xffffffffu, sum, o);
        if (lane == 0) {
            logits[(size_t)e * H + h] = sum;
            atomicMax(&mkey[d * H + h], f2key(sum));
        }
    }
}

// ---------------- GATv2 edge pass B: exp + den + unnormalized aggregate ----
__global__ void k_edge_agg(const float* __restrict__ xl,
                           const int* __restrict__ ei,
                           const float* __restrict__ logits,
                           const int* __restrict__ mkey,
                           float* __restrict__ den,
                           float* __restrict__ acc,
                           int H, int Ch)
{
    int e = (blockIdx.x * blockDim.x + threadIdx.x) >> 5;
    int lane = threadIdx.x & 31;
    if (e >= EPLUS) return;
    int s, d;
    if (e < NEDGES) { s = ei[e]; d = ei[NEDGES + e]; }
    else            { s = d = e - NEDGES; }
    const float4* pl = (const float4*)(xl + (size_t)s * HID);
    float* pd = acc + (size_t)d * HID;
    int Q = Ch >> 2;
    for (int h = 0; h < H; h++) {
        float m  = key2f(mkey[d * H + h]);
        float ex = expf(logits[(size_t)e * H + h] - m);
        if (lane == 0) atomicAdd(&den[d * H + h], ex);
        for (int q = lane; q < Q; q += 32) {
            float4 l4 = pl[h * Q + q];
            int c = h * Ch + q * 4;
            atomicAdd(&pd[c + 0], ex * l4.x);
            atomicAdd(&pd[c + 1], ex * l4.y);
            atomicAdd(&pd[c + 2], ex * l4.z);
            atomicAdd(&pd[c + 3], ex * l4.w);
        }
    }
}

// ---------------- normalize + bias + optional ELU --------------------------
__global__ void k_norm(float* __restrict__ acc, const float* __restrict__ den,
                       const float* __restrict__ bias, int H, int Ch, int elu)
{
    int idx = blockIdx.x * blockDim.x + threadIdx.x;
    if (idx >= NNODES * HID) return;
    int n = idx / HID, j = idx % HID;
    float v = acc[idx] / den[n * H + j / Ch] + bias[j];
    if (elu) v = v > 0.f ? v : expm1f(v);
    acc[idx] = v;
}

// ---------------- GCN ------------------------------------------------------
__global__ void k_deg(const int* __restrict__ ei, float* __restrict__ deg) {
    int e = blockIdx.x * blockDim.x + threadIdx.x;
    if (e >= EPLUS) return;
    int d = (e < NEDGES) ? ei[NEDGES + e] : e - NEDGES;
    atomicAdd(&deg[d], 1.f);
}
__global__ void k_dinv(float* __restrict__ deg) {
    int n = blockIdx.x * blockDim.x + threadIdx.x;
    if (n >= NNODES) return;
    deg[n] = rsqrtf(fmaxf(deg[n], 1.f));
}
__global__ void k_gcn_agg(const float* __restrict__ xw,
                          const int* __restrict__ ei,
                          const float* __restrict__ dinv,
                          float* __restrict__ acc)
{
    int e = (blockIdx.x * blockDim.x + threadIdx.x) >> 5;
    int lane = threadIdx.x & 31;
    if (e >= EPLUS) return;
    int s, d;
    if (e < NEDGES) { s = ei[e]; d = ei[NEDGES + e]; }
    else            { s = d = e - NEDGES; }
    float nrm = dinv[s] * dinv[d];
    const float4* ps = (const float4*)(xw + (size_t)s * HID);
    float* pd = acc + (size_t)d * HID;
    for (int q = lane; q < HID / 4; q += 32) {
        float4 v4 = ps[q];
        int c = q * 4;
        atomicAdd(&pd[c + 0], nrm * v4.x);
        atomicAdd(&pd[c + 1], nrm * v4.y);
        atomicAdd(&pd[c + 2], nrm * v4.z);
        atomicAdd(&pd[c + 3], nrm * v4.w);
    }
}
__global__ void k_relu_bias(float* __restrict__ h, const float* __restrict__ bg) {
    int idx = blockIdx.x * blockDim.x + threadIdx.x;
    if (idx >= NNODES * HID) return;
    h[idx] = fmaxf(h[idx] + bg[idx % HID], 0.f);
}

// ---------------- pooling --------------------------------------------------
__global__ void k_cnt(const int* __restrict__ batch, float* __restrict__ cnt) {
    int n = blockIdx.x * blockDim.x + threadIdx.x;
    if (n >= NNODES) return;
    atomicAdd(&cnt[batch[n]], 1.f);
}
__global__ void k_pool(const float* __restrict__ h,
                       const int* __restrict__ batch,
                       int* __restrict__ gmax, float* __restrict__ gsum)
{
    int idx = blockIdx.x * blockDim.x + threadIdx.x;
    if (idx >= NNODES * HID) return;
    int n = idx / HID, c = idx % HID;
    int g = batch[n];
    float v = h[idx];                       // v >= 0 after relu
    atomicMax(&gmax[g * HID + c], __float_as_int(v));
    atomicAdd(&gsum[g * HID + c], v);
}
__global__ void k_final(const int* __restrict__ gmax, const float* __restrict__ gsum,
                        const float* __restrict__ cnt, float* __restrict__ out)
{
    int idx = blockIdx.x * blockDim.x + threadIdx.x;
    if (idx >= NGRAPH * HID) return;
    int g = idx / HID, c = idx % HID;
    out[(size_t)g * (2 * HID) + c]       = __int_as_float(gmax[idx]);
    out[(size_t)g * (2 * HID) + HID + c] = gsum[idx] / fmaxf(cnt[g], 1.f);
}

// ---------------- launch ---------------------------------------------------
extern "C" void kernel_launch(void* const* d_in, const int* in_sizes, int n_in,
                              void* d_out, int out_size)
{
    const float* x     = (const float*)d_in[0];
    const int*   ei    = (const int*)d_in[1];     // int32 (JAX x64 disabled)
    const int*   batch = (const int*)d_in[2];     // int32
    const float* Wl1 = (const float*)d_in[3];
    const float* Wr1 = (const float*)d_in[4];
    const float* a1  = (const float*)d_in[5];
    const float* b1  = (const float*)d_in[6];
    const float* Wl2 = (const float*)d_in[7];
    const float* Wr2 = (const float*)d_in[8];
    const float* a2  = (const float*)d_in[9];
    const float* b2  = (const float*)d_in[10];
    const float* Wg  = (const float*)d_in[11];
    const float* bg  = (const float*)d_in[12];
    float* out = (float*)d_out;

    float *A, *B, *C, *logits, *den, *deg, *gsum, *cnt;
    int *mkey, *gmax;
    cudaGetSymbolAddress((void**)&A,      g_bufA);
    cudaGetSymbolAddress((void**)&B,      g_bufB);
    cudaGetSymbolAddress((void**)&C,      g_bufC);
    cudaGetSymbolAddress((void**)&logits, g_logits);
    cudaGetSymbolAddress((void**)&mkey,   g_mkey);
    cudaGetSymbolAddress((void**)&den,    g_den);
    cudaGetSymbolAddress((void**)&deg,    g_deg);
    cudaGetSymbolAddress((void**)&gmax,   g_gmax);
    cudaGetSymbolAddress((void**)&gsum,   g_gsum);
    cudaGetSymbolAddress((void**)&cnt,    g_cnt);

    const int T = 256;
    dim3 gg(HID / BN, (NNODES + BM - 1) / BM);           // (5, 391)
    int eb  = (EPLUS * 32 + T - 1) / T;                  // warp per edge
    int nhb = (NNODES * HID + T - 1) / T;
    int nb  = (NNODES + T - 1) / T;
    int epb = (EPLUS + T - 1) / T;
    int ghb = (NGRAPH * HID + T - 1) / T;

    // ---- Layer 1: GATv2 (heads=10, C=64) ----
    k_gemm<<<gg, T>>>(x, Wl1, A, NNODES, INDIM, HID);
    k_gemm<<<gg, T>>>(x, Wr1, B, NNODES, INDIM, HID);
    k_fill_i<<<(NNODES * HEADS + T - 1) / T, T>>>(mkey, INTMIN_, NNODES * HEADS);
    k_fill_f<<<(NNODES * HEADS + T - 1) / T, T>>>(den, 0.f, NNODES * HEADS);
    k_fill_f<<<nhb, T>>>(C, 0.f, NNODES * HID);
    k_edge_logits<<<eb, T>>>(A, B, ei, a1, logits, mkey, HEADS, C1);
    k_edge_agg<<<eb, T>>>(A, ei, logits, mkey, den, C, HEADS, C1);
    k_norm<<<nhb, T>>>(C, den, b1, HEADS, C1, 1 /*elu*/);

    // ---- Layer 2: GATv2 (heads=1, C=640) ----
    k_gemm<<<gg, T>>>(C, Wl2, A, NNODES, HID, HID);
    k_gemm<<<gg, T>>>(C, Wr2, B, NNODES, HID, HID);
    k_fill_i<<<nb, T>>>(mkey, INTMIN_, NNODES);
    k_fill_f<<<nb, T>>>(den, 0.f, NNODES);
    k_fill_f<<<nhb, T>>>(C, 0.f, NNODES * HID);
    k_edge_logits<<<eb, T>>>(A, B, ei, a2, logits, mkey, 1, HID);
    k_edge_agg<<<eb, T>>>(A, ei, logits, mkey, den, C, 1, HID);
    k_norm<<<nhb, T>>>(C, den, b2, 1, HID, 0);

    // ---- Layer 3: GCN ----
    k_gemm<<<gg, T>>>(C, Wg, A, NNODES, HID, HID);
    k_fill_f<<<nb, T>>>(deg, 0.f, NNODES);
    k_deg<<<epb, T>>>(ei, deg);
    k_dinv<<<nb, T>>>(deg);
    k_fill_f<<<nhb, T>>>(B, 0.f, NNODES * HID);
    k_gcn_agg<<<eb, T>>>(A, ei, deg, B);
    k_relu_bias<<<nhb, T>>>(B, bg);

    // ---- Global max + mean pool ----
    k_fill_i<<<ghb, T>>>(gmax, 0, NGRAPH * HID);   // relu => values >= 0
    k_fill_f<<<ghb, T>>>(gsum, 0.f, NGRAPH * HID);
    k_fill_f<<<(NGRAPH + T - 1) / T, T>>>(cnt, 0.f, NGRAPH);
    k_cnt<<<nb, T>>>(batch, cnt);
    k_pool<<<nhb, T>>>(B, batch, gmax, gsum);
    k_final<<<ghb, T>>>(gmax, gsum, cnt, out);
}

// round 10
// speedup vs baseline: 1.3925x; 1.3925x over previous
#include <cuda_runtime.h>
#include <cuda_bf16.h>
#include <cstdint>

#define NNODES 50000
#define NEDGES 150000
#define EPLUS  (NEDGES + NNODES)   // edges + self loops = 200000
#define NGRAPH 1024
#define INDIM  78
#define KP1    128                 // layer-1 K padded to 128
#define HID    640
#define HEADS  10
#define C1     64
#define NEGSLOPE 0.2f
#define INTMIN_ (-2147483647 - 1)

// ---------------- scratch (static __device__ — no allocations allowed) -----
__device__ float g_bufA[(size_t)NNODES * HID];
__device__ float g_bufB[(size_t)NNODES * HID];
__device__ float g_bufC[(size_t)NNODES * HID];
__device__ float g_logits[(size_t)EPLUS * HEADS];
__device__ int   g_mkey[NNODES * HEADS];
__device__ float g_den [NNODES * HEADS];
__device__ float g_deg [NNODES];
__device__ int   g_gmax[NGRAPH * HID];
__device__ float g_gsum[NGRAPH * HID];
__device__ float g_cnt [NGRAPH];
// bf16 split buffers
__device__ __nv_bfloat16 g_xhi[(size_t)NNODES * KP1];
__device__ __nv_bfloat16 g_xlo[(size_t)NNODES * KP1];
__device__ __nv_bfloat16 g_hhi[(size_t)NNODES * HID];
__device__ __nv_bfloat16 g_hlo[(size_t)NNODES * HID];
__device__ __nv_bfloat16 g_w1lhi[HID * KP1], g_w1llo[HID * KP1];
__device__ __nv_bfloat16 g_w1rhi[HID * KP1], g_w1rlo[HID * KP1];
__device__ __nv_bfloat16 g_w2lhi[HID * HID], g_w2llo[HID * HID];
__device__ __nv_bfloat16 g_w2rhi[HID * HID], g_w2rlo[HID * HID];
__device__ __nv_bfloat16 g_wghi [HID * HID], g_wglo [HID * HID];

// ---------------- helpers --------------------------------------------------
__device__ __forceinline__ int f2key(float f) {
    int i = __float_as_int(f);
    return i >= 0 ? i : (i ^ 0x7FFFFFFF);
}
__device__ __forceinline__ float key2f(int k) {
    return __int_as_float(k >= 0 ? k : (k ^ 0x7FFFFFFF));
}
__device__ __forceinline__ uint32_t smem_u32(const void* p) {
    return (uint32_t)__cvta_generic_to_shared(p);
}

#define LDSM4(r0, r1, r2, r3, addr) \
    asm volatile("ldmatrix.sync.aligned.m8n8.x4.shared.b16 {%0,%1,%2,%3}, [%4];" \
                 : "=r"(r0), "=r"(r1), "=r"(r2), "=r"(r3) : "r"(addr))

#define MMA16816(c, a0, a1, a2, a3, b0, b1) \
    asm volatile("mma.sync.aligned.m16n8k16.row.col.f32.bf16.bf16.f32 " \
                 "{%0,%1,%2,%3}, {%4,%5,%6,%7}, {%8,%9}, {%0,%1,%2,%3};" \
                 : "+f"((c)[0]), "+f"((c)[1]), "+f"((c)[2]), "+f"((c)[3]) \
                 : "r"(a0), "r"(a1), "r"(a2), "r"(a3), "r"(b0), "r"(b1))

// ---------------- fills ----------------------------------------------------
__global__ void k_fill_f(float* p, float v, int n) {
    int i = blockIdx.x * blockDim.x + threadIdx.x;
    if (i < n) p[i] = v;
}
__global__ void k_fill_i(int* p, int v, int n) {
    int i = blockIdx.x * blockDim.x + threadIdx.x;
    if (i < n) p[i] = v;
}

// ---------------- bf16 hi/lo split prep ------------------------------------
__global__ void k_split(const float* __restrict__ src,
                        __nv_bfloat16* __restrict__ hi, __nv_bfloat16* __restrict__ lo,
                        int M, int K, int Kp)
{
    int idx = blockIdx.x * blockDim.x + threadIdx.x;
    if (idx >= M * Kp) return;
    int r = idx / Kp, k = idx - r * Kp;
    float v = (k < K) ? src[(size_t)r * K + k] : 0.f;
    __nv_bfloat16 h = __float2bfloat16(v);
    hi[idx] = h;
    lo[idx] = __float2bfloat16(v - __bfloat162float(h));
}
// W [K,N] row-major -> hi/lo [N,Kp] (transposed, zero pad)
__global__ void k_splitT(const float* __restrict__ W,
                         __nv_bfloat16* __restrict__ hi, __nv_bfloat16* __restrict__ lo,
                         int K, int N, int Kp)
{
    int idx = blockIdx.x * blockDim.x + threadIdx.x;
    if (idx >= N * Kp) return;
    int n = idx / Kp, k = idx - n * Kp;
    float v = (k < K) ? W[(size_t)k * N + n] : 0.f;
    __nv_bfloat16 h = __float2bfloat16(v);
    hi[idx] = h;
    lo[idx] = __float2bfloat16(v - __bfloat162float(h));
}

// ---------------- split-bf16 HMMA GEMM -------------------------------------
// C[M,N] = (Ahi+Alo)[M,K] @ (Bhi+Blo)[N,K]^T, fp32 accum.
// 3-term: AhBh + AhBl + AlBh (drops lo*lo ~2^-16).
// CTA 128x128, 8 warps (4m x 2n), warp 32x64, K-step 16.
// smem rows padded to 24 bf16 (48B) -> conflict-free ldmatrix.
#define SLD 24

__global__ __launch_bounds__(256, 2)
void k_hgemm(const __nv_bfloat16* __restrict__ Ahi, const __nv_bfloat16* __restrict__ Alo,
             const __nv_bfloat16* __restrict__ Bhi, const __nv_bfloat16* __restrict__ Blo,
             float* __restrict__ C, int M, int N, int K)
{
    __shared__ __align__(16) __nv_bfloat16 sAh[128 * SLD], sAl[128 * SLD];
    __shared__ __align__(16) __nv_bfloat16 sBh[128 * SLD], sBl[128 * SLD];

    const int tid = threadIdx.x, lane = tid & 31, wid = tid >> 5;
    const int wm = wid & 3, wn = wid >> 2;
    const int bm = blockIdx.y * 128, bn = blockIdx.x * 128;

    float c[2][8][4];
    #pragma unroll
    for (int i = 0; i < 2; i++)
        #pragma unroll
        for (int j = 0; j < 8; j++)
            #pragma unroll
            for (int q = 0; q < 4; q++) c[i][j][q] = 0.f;

    const int lrow = tid >> 1, lhalf = tid & 1;      // global->smem copy role
    const uint32_t aAh = smem_u32(sAh), aAl = smem_u32(sAl);
    const uint32_t aBh = smem_u32(sBh), aBl = smem_u32(sBl);
    const uint32_t sw_off = (uint32_t)(lrow * 48 + lhalf * 16);

    // ldmatrix lane address components
    const uint32_t a_mr = (lane & 7) + ((lane >> 3) & 1) * 8;   // row within m16
    const uint32_t a_kc = (lane >> 4) * 8;                      // k col 0/8
    const uint32_t b_nr = ((lane >> 4) & 1) * 8 + (lane & 7);   // row within n16
    const uint32_t b_kc = ((lane >> 3) & 1) * 8;

    const bool va = (bm + lrow) < M;
    const __nv_bfloat16* pAh = Ahi + (size_t)(bm + lrow) * K + lhalf * 8;
    const __nv_bfloat16* pAl = Alo + (size_t)(bm + lrow) * K + lhalf * 8;
    const __nv_bfloat16* pBh = Bhi + (size_t)(bn + lrow) * K + lhalf * 8;
    const __nv_bfloat16* pBl = Blo + (size_t)(bn + lrow) * K + lhalf * 8;

    for (int k0 = 0; k0 < K; k0 += 16) {
        __syncthreads();
        uint4 z = make_uint4(0u, 0u, 0u, 0u);
        *(uint4*)((char*)sAh + sw_off) = va ? *(const uint4*)(pAh + k0) : z;
        *(uint4*)((char*)sAl + sw_off) = va ? *(const uint4*)(pAl + k0) : z;
        *(uint4*)((char*)sBh + sw_off) = *(const uint4*)(pBh + k0);
        *(uint4*)((char*)sBl + sw_off) = *(const uint4*)(pBl + k0);
        __syncthreads();

        #pragma unroll
        for (int mt = 0; mt < 2; mt++) {
            uint32_t aaddr = (uint32_t)((wm * 32 + mt * 16 + a_mr) * 48 + a_kc * 2);
            uint32_t ah0, ah1, ah2, ah3, al0, al1, al2, al3;
            LDSM4(ah0, ah1, ah2, ah3, aAh + aaddr);
            LDSM4(al0, al1, al2, al3, aAl + aaddr);
            #pragma unroll
            for (int bg = 0; bg < 4; bg++) {
                uint32_t baddr = (uint32_t)((wn * 64 + bg * 16 + b_nr) * 48 + b_kc * 2);
                uint32_t bh0, bh1, bh2, bh3, bl0, bl1, bl2, bl3;
                LDSM4(bh0, bh1, bh2, bh3, aBh + baddr);
                LDSM4(bl0, bl1, bl2, bl3, aBl + baddr);
                float* c0 = c[mt][bg * 2];
                float* c1 = c[mt][bg * 2 + 1];
                MMA16816(c0, ah0, ah1, ah2, ah3, bh0, bh1);
                MMA16816(c0, ah0, ah1, ah2, ah3, bl0, bl1);
                MMA16816(c0, al0, al1, al2, al3, bh0, bh1);
                MMA16816(c1, ah0, ah1, ah2, ah3, bh2, bh3);
                MMA16816(c1, ah0, ah1, ah2, ah3, bl2, bl3);
                MMA16816(c1, al0, al1, al2, al3, bh2, bh3);
            }
        }
    }

    // epilogue: c0,c1 at (row, col..col+1); c2,c3 at (row+8, ...)
    const int rbase = bm + wm * 32 + (lane >> 2);
    const int cbase = bn + wn * 64 + (lane & 3) * 2;
    #pragma unroll
    for (int mt = 0; mt < 2; mt++) {
        #pragma unroll
        for (int nt = 0; nt < 8; nt++) {
            int rr = rbase + mt * 16;
            int cc = cbase + nt * 8;
            if (rr < M) {
                float2 v = make_float2(c[mt][nt][0], c[mt][nt][1]);
                *(float2*)&C[(size_t)rr * N + cc] = v;
            }
            if (rr + 8 < M) {
                float2 v = make_float2(c[mt][nt][2], c[mt][nt][3]);
                *(float2*)&C[(size_t)(rr + 8) * N + cc] = v;
            }
        }
    }
}

// ---------------- GATv2 edge pass A: logits + scatter max ------------------
__global__ void k_edge_logits(const float* __restrict__ xl,
                              const float* __restrict__ xr,
                              const int* __restrict__ ei,
                              const float* __restrict__ att,
                              float* __restrict__ logits,
                              int* __restrict__ mkey,
                              int H, int Ch)
{
    int e = (blockIdx.x * blockDim.x + threadIdx.x) >> 5;
    int lane = threadIdx.x & 31;
    if (e >= EPLUS) return;
    int s, d;
    if (e < NEDGES) { s = ei[e]; d = ei[NEDGES + e]; }
    else            { s = d = e - NEDGES; }
    const float4* pl = (const float4*)(xl + (size_t)s * HID);
    const float4* pr = (const float4*)(xr + (size_t)d * HID);
    const float4* pa = (const float4*)att;
    int Q = Ch >> 2;
    for (int h = 0; h < H; h++) {
        float sum = 0.f;
        for (int q = lane; q < Q; q += 32) {
            float4 l4 = pl[h * Q + q];
            float4 r4 = pr[h * Q + q];
            float4 a4 = pa[h * Q + q];
            float v;
            v = l4.x + r4.x; v = v > 0.f ? v : NEGSLOPE * v; sum += v * a4.x;
            v = l4.y + r4.y; v = v > 0.f ? v : NEGSLOPE * v; sum += v * a4.y;
            v = l4.z + r4.z; v = v > 0.f ? v : NEGSLOPE * v; sum += v * a4.z;
            v = l4.w + r4.w; v = v > 0.f ? v : NEGSLOPE * v; sum += v * a4.w;
        }
        #pragma unroll
        for (int o = 16; o > 0; o >>= 1)
            sum += __shfl_xor_sync(0xffffffffu, sum, o);
        if (lane == 0) {
            logits[(size_t)e * H + h] = sum;
            atomicMax(&mkey[d * H + h], f2key(sum));
        }
    }
}

// ---------------- GATv2 edge pass B: exp + den + unnormalized aggregate ----
__global__ void k_edge_agg(const float* __restrict__ xl,
                           const int* __restrict__ ei,
                           const float* __restrict__ logits,
                           const int* __restrict__ mkey,
                           float* __restrict__ den,
                           float* __restrict__ acc,
                           int H, int Ch)
{
    int e = (blockIdx.x * blockDim.x + threadIdx.x) >> 5;
    int lane = threadIdx.x & 31;
    if (e >= EPLUS) return;
    int s, d;
    if (e < NEDGES) { s = ei[e]; d = ei[NEDGES + e]; }
    else            { s = d = e - NEDGES; }
    const float4* pl = (const float4*)(xl + (size_t)s * HID);
    float* pd = acc + (size_t)d * HID;
    int Q = Ch >> 2;
    for (int h = 0; h < H; h++) {
        float m  = key2f(mkey[d * H + h]);
        float ex = expf(logits[(size_t)e * H + h] - m);
        if (lane == 0) atomicAdd(&den[d * H + h], ex);
        for (int q = lane; q < Q; q += 32) {
            float4 l4 = pl[h * Q + q];
            int c = h * Ch + q * 4;
            atomicAdd(&pd[c + 0], ex * l4.x);
            atomicAdd(&pd[c + 1], ex * l4.y);
            atomicAdd(&pd[c + 2], ex * l4.z);
            atomicAdd(&pd[c + 3], ex * l4.w);
        }
    }
}

// ---------------- normalize + bias + optional ELU --------------------------
__global__ void k_norm(float* __restrict__ acc, const float* __restrict__ den,
                       const float* __restrict__ bias, int H, int Ch, int elu)
{
    int idx = blockIdx.x * blockDim.x + threadIdx.x;
    if (idx >= NNODES * HID) return;
    int n = idx / HID, j = idx % HID;
    float v = acc[idx] / den[n * H + j / Ch] + bias[j];
    if (elu) v = v > 0.f ? v : expm1f(v);
    acc[idx] = v;
}

// ---------------- GCN ------------------------------------------------------
__global__ void k_deg(const int* __restrict__ ei, float* __restrict__ deg) {
    int e = blockIdx.x * blockDim.x + threadIdx.x;
    if (e >= EPLUS) return;
    int d = (e < NEDGES) ? ei[NEDGES + e] : e - NEDGES;
    atomicAdd(&deg[d], 1.f);
}
__global__ void k_dinv(float* __restrict__ deg) {
    int n = blockIdx.x * blockDim.x + threadIdx.x;
    if (n >= NNODES) return;
    deg[n] = rsqrtf(fmaxf(deg[n], 1.f));
}
__global__ void k_gcn_agg(const float* __restrict__ xw,
                          const int* __restrict__ ei,
                          const float* __restrict__ dinv,
                          float* __restrict__ acc)
{
    int e = (blockIdx.x * blockDim.x + threadIdx.x) >> 5;
    int lane = threadIdx.x & 31;
    if (e >= EPLUS) return;
    int s, d;
    if (e < NEDGES) { s = ei[e]; d = ei[NEDGES + e]; }
    else            { s = d = e - NEDGES; }
    float nrm = dinv[s] * dinv[d];
    const float4* ps = (const float4*)(xw + (size_t)s * HID);
    float* pd = acc + (size_t)d * HID;
    for (int q = lane; q < HID / 4; q += 32) {
        float4 v4 = ps[q];
        int c = q * 4;
        atomicAdd(&pd[c + 0], nrm * v4.x);
        atomicAdd(&pd[c + 1], nrm * v4.y);
        atomicAdd(&pd[c + 2], nrm * v4.z);
        atomicAdd(&pd[c + 3], nrm * v4.w);
    }
}
__global__ void k_relu_bias(float* __restrict__ h, const float* __restrict__ bg) {
    int idx = blockIdx.x * blockDim.x + threadIdx.x;
    if (idx >= NNODES * HID) return;
    h[idx] = fmaxf(h[idx] + bg[idx % HID], 0.f);
}

// ---------------- pooling --------------------------------------------------
__global__ void k_cnt(const int* __restrict__ batch, float* __restrict__ cnt) {
    int n = blockIdx.x * blockDim.x + threadIdx.x;
    if (n >= NNODES) return;
    atomicAdd(&cnt[batch[n]], 1.f);
}
__global__ void k_pool(const float* __restrict__ h,
                       const int* __restrict__ batch,
                       int* __restrict__ gmax, float* __restrict__ gsum)
{
    int idx = blockIdx.x * blockDim.x + threadIdx.x;
    if (idx >= NNODES * HID) return;
    int n = idx / HID, c = idx % HID;
    int g = batch[n];
    float v = h[idx];
    atomicMax(&gmax[g * HID + c], __float_as_int(v));
    atomicAdd(&gsum[g * HID + c], v);
}
__global__ void k_final(const int* __restrict__ gmax, const float* __restrict__ gsum,
                        const float* __restrict__ cnt, float* __restrict__ out)
{
    int idx = blockIdx.x * blockDim.x + threadIdx.x;
    if (idx >= NGRAPH * HID) return;
    int g = idx / HID, c = idx % HID;
    out[(size_t)g * (2 * HID) + c]       = __int_as_float(gmax[idx]);
    out[(size_t)g * (2 * HID) + HID + c] = gsum[idx] / fmaxf(cnt[g], 1.f);
}

// ---------------- launch ---------------------------------------------------
extern "C" void kernel_launch(void* const* d_in, const int* in_sizes, int n_in,
                              void* d_out, int out_size)
{
    const float* x     = (const float*)d_in[0];
    const int*   ei    = (const int*)d_in[1];
    const int*   batch = (const int*)d_in[2];
    const float* Wl1 = (const float*)d_in[3];
    const float* Wr1 = (const float*)d_in[4];
    const float* a1  = (const float*)d_in[5];
    const float* b1  = (const float*)d_in[6];
    const float* Wl2 = (const float*)d_in[7];
    const float* Wr2 = (const float*)d_in[8];
    const float* a2  = (const float*)d_in[9];
    const float* b2  = (const float*)d_in[10];
    const float* Wg  = (const float*)d_in[11];
    const float* bg  = (const float*)d_in[12];
    float* out = (float*)d_out;

    float *A, *B, *C, *logits, *den, *deg, *gsum, *cnt;
    int *mkey, *gmax;
    __nv_bfloat16 *xhi, *xlo, *hhi, *hlo;
    __nv_bfloat16 *w1lhi, *w1llo, *w1rhi, *w1rlo;
    __nv_bfloat16 *w2lhi, *w2llo, *w2rhi, *w2rlo, *wghi, *wglo;
    cudaGetSymbolAddress((void**)&A,      g_bufA);
    cudaGetSymbolAddress((void**)&B,      g_bufB);
    cudaGetSymbolAddress((void**)&C,      g_bufC);
    cudaGetSymbolAddress((void**)&logits, g_logits);
    cudaGetSymbolAddress((void**)&mkey,   g_mkey);
    cudaGetSymbolAddress((void**)&den,    g_den);
    cudaGetSymbolAddress((void**)&deg,    g_deg);
    cudaGetSymbolAddress((void**)&gmax,   g_gmax);
    cudaGetSymbolAddress((void**)&gsum,   g_gsum);
    cudaGetSymbolAddress((void**)&cnt,    g_cnt);
    cudaGetSymbolAddress((void**)&xhi,    g_xhi);
    cudaGetSymbolAddress((void**)&xlo,    g_xlo);
    cudaGetSymbolAddress((void**)&hhi,    g_hhi);
    cudaGetSymbolAddress((void**)&hlo,    g_hlo);
    cudaGetSymbolAddress((void**)&w1lhi,  g_w1lhi);
    cudaGetSymbolAddress((void**)&w1llo,  g_w1llo);
    cudaGetSymbolAddress((void**)&w1rhi,  g_w1rhi);
    cudaGetSymbolAddress((void**)&w1rlo,  g_w1rlo);
    cudaGetSymbolAddress((void**)&w2lhi,  g_w2lhi);
    cudaGetSymbolAddress((void**)&w2llo,  g_w2llo);
    cudaGetSymbolAddress((void**)&w2rhi,  g_w2rhi);
    cudaGetSymbolAddress((void**)&w2rlo,  g_w2rlo);
    cudaGetSymbolAddress((void**)&wghi,   g_wghi);
    cudaGetSymbolAddress((void**)&wglo,   g_wglo);

    const int T = 256;
    dim3 gg(HID / 128, (NNODES + 127) / 128);            // (5, 391)
    int eb  = (EPLUS * 32 + T - 1) / T;
    int nhb = (NNODES * HID + T - 1) / T;
    int nb  = (NNODES + T - 1) / T;
    int epb = (EPLUS + T - 1) / T;
    int ghb = (NGRAPH * HID + T - 1) / T;
    int xsb = (NNODES * KP1 + T - 1) / T;
    int w1b = (HID * KP1 + T - 1) / T;
    int w2b = (HID * HID + T - 1) / T;

    // ---- prep: bf16 hi/lo splits (weights + x) ----
    k_split <<<xsb, T>>>(x, xhi, xlo, NNODES, INDIM, KP1);
    k_splitT<<<w1b, T>>>(Wl1, w1lhi, w1llo, INDIM, HID, KP1);
    k_splitT<<<w1b, T>>>(Wr1, w1rhi, w1rlo, INDIM, HID, KP1);
    k_splitT<<<w2b, T>>>(Wl2, w2lhi, w2llo, HID, HID, HID);
    k_splitT<<<w2b, T>>>(Wr2, w2rhi, w2rlo, HID, HID, HID);
    k_splitT<<<w2b, T>>>(Wg,  wghi,  wglo,  HID, HID, HID);

    // ---- Layer 1: GATv2 (heads=10, C=64) ----
    k_hgemm<<<gg, T>>>(xhi, xlo, w1lhi, w1llo, A, NNODES, HID, KP1);
    k_hgemm<<<gg, T>>>(xhi, xlo, w1rhi, w1rlo, B, NNODES, HID, KP1);
    k_fill_i<<<(NNODES * HEADS + T - 1) / T, T>>>(mkey, INTMIN_, NNODES * HEADS);
    k_fill_f<<<(NNODES * HEADS + T - 1) / T, T>>>(den, 0.f, NNODES * HEADS);
    k_fill_f<<<nhb, T>>>(C, 0.f, NNODES * HID);
    k_edge_logits<<<eb, T>>>(A, B, ei, a1, logits, mkey, HEADS, C1);
    k_edge_agg<<<eb, T>>>(A, ei, logits, mkey, den, C, HEADS, C1);
    k_norm<<<nhb, T>>>(C, den, b1, HEADS, C1, 1);

    // ---- Layer 2: GATv2 (heads=1, C=640) ----
    k_split<<<nhb, T>>>(C, hhi, hlo, NNODES, HID, HID);
    k_hgemm<<<gg, T>>>(hhi, hlo, w2lhi, w2llo, A, NNODES, HID, HID);
    k_hgemm<<<gg, T>>>(hhi, hlo, w2rhi, w2rlo, B, NNODES, HID, HID);
    k_fill_i<<<nb, T>>>(mkey, INTMIN_, NNODES);
    k_fill_f<<<nb, T>>>(den, 0.f, NNODES);
    k_fill_f<<<nhb, T>>>(C, 0.f, NNODES * HID);
    k_edge_logits<<<eb, T>>>(A, B, ei, a2, logits, mkey, 1, HID);
    k_edge_agg<<<eb, T>>>(A, ei, logits, mkey, den, C, 1, HID);
    k_norm<<<nhb, T>>>(C, den, b2, 1, HID, 0);

    // ---- Layer 3: GCN ----
    k_split<<<nhb, T>>>(C, hhi, hlo, NNODES, HID, HID);
    k_hgemm<<<gg, T>>>(hhi, hlo, wghi, wglo, A, NNODES, HID, HID);
    k_fill_f<<<nb, T>>>(deg, 0.f, NNODES);
    k_deg<<<epb, T>>>(ei, deg);
    k_dinv<<<nb, T>>>(deg);
    k_fill_f<<<nhb, T>>>(B, 0.f, NNODES * HID);
    k_gcn_agg<<<eb, T>>>(A, ei, deg, B);
    k_relu_bias<<<nhb, T>>>(B, bg);

    // ---- Global max + mean pool ----
    k_fill_i<<<ghb, T>>>(gmax, 0, NGRAPH * HID);
    k_fill_f<<<ghb, T>>>(gsum, 0.f, NGRAPH * HID);
    k_fill_f<<<(NGRAPH + T - 1) / T, T>>>(cnt, 0.f, NGRAPH);
    k_cnt<<<nb, T>>>(batch, cnt);
    k_pool<<<nhb, T>>>(B, batch, gmax, gsum);
    k_final<<<ghb, T>>>(gmax, gsum, cnt, out);
}

// round 11
// speedup vs baseline: 2.1961x; 1.5771x over previous
#include <cuda_runtime.h>
#include <cuda_bf16.h>
#include <cstdint>

#define NNODES 50000
#define NEDGES 150000
#define EPLUS  (NEDGES + NNODES)   // edges + self loops = 200000
#define NGRAPH 1024
#define INDIM  78
#define KP1    128                 // layer-1 K padded to 128
#define HID    640
#define HEADS  10
#define C1     64
#define NEGSLOPE 0.2f

// ---------------- scratch (static __device__ — no allocations allowed) -----
__device__ __align__(128) float g_bufA[(size_t)NNODES * HID];
__device__ __align__(128) float g_bufB[(size_t)NNODES * HID];
__device__ __align__(128) float g_logits[(size_t)EPLUS * HEADS];
__device__ float g_dinv[NNODES];
__device__ int   g_rowptr[NNODES + 1];
__device__ int   g_cntbuf[NNODES];
__device__ int   g_csr_src[EPLUS];
__device__ int   g_csr_eid[EPLUS];
__device__ int   g_gmax[NGRAPH * HID];
__device__ float g_gsum[NGRAPH * HID];
__device__ float g_cnt [NGRAPH];
// bf16 split buffers
__device__ __align__(128) __nv_bfloat16 g_xhi[(size_t)NNODES * KP1];
__device__ __align__(128) __nv_bfloat16 g_xlo[(size_t)NNODES * KP1];
__device__ __align__(128) __nv_bfloat16 g_hhi[(size_t)NNODES * HID];
__device__ __align__(128) __nv_bfloat16 g_hlo[(size_t)NNODES * HID];
__device__ __align__(128) __nv_bfloat16 g_w1lhi[HID * KP1], g_w1llo[HID * KP1];
__device__ __align__(128) __nv_bfloat16 g_w1rhi[HID * KP1], g_w1rlo[HID * KP1];
__device__ __align__(128) __nv_bfloat16 g_w2lhi[HID * HID], g_w2llo[HID * HID];
__device__ __align__(128) __nv_bfloat16 g_w2rhi[HID * HID], g_w2rlo[HID * HID];
__device__ __align__(128) __nv_bfloat16 g_wghi [HID * HID], g_wglo [HID * HID];

// ---------------- helpers --------------------------------------------------
__device__ __forceinline__ uint32_t smem_u32(const void* p) {
    return (uint32_t)__cvta_generic_to_shared(p);
}
#define LDSM4(r0, r1, r2, r3, addr) \
    asm volatile("ldmatrix.sync.aligned.m8n8.x4.shared.b16 {%0,%1,%2,%3}, [%4];" \
                 : "=r"(r0), "=r"(r1), "=r"(r2), "=r"(r3) : "r"(addr))
#define MMA16816(c, a0, a1, a2, a3, b0, b1) \
    asm volatile("mma.sync.aligned.m16n8k16.row.col.f32.bf16.bf16.f32 " \
                 "{%0,%1,%2,%3}, {%4,%5,%6,%7}, {%8,%9}, {%0,%1,%2,%3};" \
                 : "+f"((c)[0]), "+f"((c)[1]), "+f"((c)[2]), "+f"((c)[3]) \
                 : "r"(a0), "r"(a1), "r"(a2), "r"(a3), "r"(b0), "r"(b1))
__device__ __forceinline__ void cpasync16(uint32_t dst, const void* src, int sz) {
    asm volatile("cp.async.cg.shared.global [%0], [%1], 16, %2;"
                 :: "r"(dst), "l"(src), "r"(sz));
}
#define CP_COMMIT asm volatile("cp.async.commit_group;")
#define CP_WAIT1  asm volatile("cp.async.wait_group 1;")
#define CP_WAIT0  asm volatile("cp.async.wait_group 0;")

// ---------------- fills ----------------------------------------------------
__global__ void k_fill_f(float* p, float v, int n) {
    int i = blockIdx.x * blockDim.x + threadIdx.x;
    if (i < n) p[i] = v;
}
__global__ void k_fill_i(int* p, int v, int n) {
    int i = blockIdx.x * blockDim.x + threadIdx.x;
    if (i < n) p[i] = v;
}

// ---------------- CSR build ------------------------------------------------
__global__ void k_count(const int* __restrict__ ei, int* __restrict__ cnt) {
    int e = blockIdx.x * blockDim.x + threadIdx.x;
    if (e >= EPLUS) return;
    int d = (e < NEDGES) ? ei[NEDGES + e] : e - NEDGES;
    atomicAdd(&cnt[d], 1);
}
__global__ void k_scan(const int* __restrict__ cnt, int* __restrict__ rowptr) {
    __shared__ int sh[1024];
    __shared__ int carry;
    if (threadIdx.x == 0) carry = 0;
    __syncthreads();
    for (int base = 0; base < NNODES; base += 1024) {
        int i = base + threadIdx.x;
        int v = (i < NNODES) ? cnt[i] : 0;
        sh[threadIdx.x] = v;
        __syncthreads();
        for (int off = 1; off < 1024; off <<= 1) {
            int t = (threadIdx.x >= off) ? sh[threadIdx.x - off] : 0;
            __syncthreads();
            sh[threadIdx.x] += t;
            __syncthreads();
        }
        if (i < NNODES) rowptr[i] = carry + sh[threadIdx.x] - v;
        __syncthreads();
        if (threadIdx.x == 1023) carry += sh[1023];
        __syncthreads();
    }
    if (threadIdx.x == 0) rowptr[NNODES] = EPLUS;
}
__global__ void k_scatter(const int* __restrict__ ei, const int* __restrict__ rowptr,
                          int* __restrict__ fill, int* __restrict__ csr_src,
                          int* __restrict__ csr_eid) {
    int e = blockIdx.x * blockDim.x + threadIdx.x;
    if (e >= EPLUS) return;
    int s, d;
    if (e < NEDGES) { s = ei[e]; d = ei[NEDGES + e]; }
    else            { s = d = e - NEDGES; }
    int pos = rowptr[d] + atomicAdd(&fill[d], 1);
    csr_src[pos] = s;
    csr_eid[pos] = e;
}
__global__ void k_dinv(const int* __restrict__ rowptr, float* __restrict__ dinv) {
    int n = blockIdx.x * blockDim.x + threadIdx.x;
    if (n >= NNODES) return;
    dinv[n] = rsqrtf((float)(rowptr[n + 1] - rowptr[n]));   // >=1 (self loop)
}

// ---------------- bf16 hi/lo split prep ------------------------------------
__global__ void k_split(const float* __restrict__ src,
                        __nv_bfloat16* __restrict__ hi, __nv_bfloat16* __restrict__ lo,
                        int M, int K, int Kp)
{
    int idx = blockIdx.x * blockDim.x + threadIdx.x;
    if (idx >= M * Kp) return;
    int r = idx / Kp, k = idx - r * Kp;
    float v = (k < K) ? src[(size_t)r * K + k] : 0.f;
    __nv_bfloat16 h = __float2bfloat16(v);
    hi[idx] = h;
    lo[idx] = __float2bfloat16(v - __bfloat162float(h));
}
__global__ void k_splitT(const float* __restrict__ W,
                         __nv_bfloat16* __restrict__ hi, __nv_bfloat16* __restrict__ lo,
                         int K, int N, int Kp)
{
    int idx = blockIdx.x * blockDim.x + threadIdx.x;
    if (idx >= N * Kp) return;
    int n = idx / Kp, k = idx - n * Kp;
    float v = (k < K) ? W[(size_t)k * N + n] : 0.f;
    __nv_bfloat16 h = __float2bfloat16(v);
    hi[idx] = h;
    lo[idx] = __float2bfloat16(v - __bfloat162float(h));
}

// ---------------- split-bf16 HMMA GEMM, cp.async double buffer -------------
// C[M,N] = (Ahi+Alo)[M,K] @ (Bhi+Blo)[N,K]^T, fp32 accum, 3-term split.
// CTA 128x128, 8 warps (4m x 2n), warp 32x64. BK=32, rows padded to 80B.
// smem: 2 stages x 4 tensors x (128 rows x 80B) = 81920B dynamic.
#define STG_T   10240               // bytes per tensor per stage (128*80)
#define STG_ALL 40960               // bytes per stage

__global__ __launch_bounds__(256, 2)
void k_hgemm(const __nv_bfloat16* __restrict__ Ahi, const __nv_bfloat16* __restrict__ Alo,
             const __nv_bfloat16* __restrict__ Bhi, const __nv_bfloat16* __restrict__ Blo,
             float* __restrict__ C, int M, int N, int K)
{
    extern __shared__ __align__(128) char smem[];
    const uint32_t sb = smem_u32(smem);
    const int tid = threadIdx.x, lane = tid & 31, wid = tid >> 5;
    const int wm = wid & 3, wn = wid >> 2;
    const int bm = blockIdx.y * 128, bn = blockIdx.x * 128;

    float c[2][8][4];
    #pragma unroll
    for (int i = 0; i < 2; i++)
        #pragma unroll
        for (int j = 0; j < 8; j++)
            #pragma unroll
            for (int q = 0; q < 4; q++) c[i][j][q] = 0.f;

    // copy roles: thread -> (row, 32B half of the 64B row payload)
    const int row = tid >> 1, half = tid & 1;
    const bool va = (bm + row) < M;
    const int szA = va ? 16 : 0;
    const char* gAh = (const char*)(Ahi + (size_t)(bm + row) * K) + half * 32;
    const char* gAl = (const char*)(Alo + (size_t)(bm + row) * K) + half * 32;
    const char* gBh = (const char*)(Bhi + (size_t)(bn + row) * K) + half * 32;
    const char* gBl = (const char*)(Blo + (size_t)(bn + row) * K) + half * 32;
    const uint32_t dOff = (uint32_t)(row * 80 + half * 32);

#define LOAD_STAGE(s, k0) do {                                              \
        uint32_t b_ = sb + (uint32_t)((s) & 1) * STG_ALL;                   \
        size_t kb_ = (size_t)(k0) * 2;                                      \
        cpasync16(b_ + 0 * STG_T + dOff,      gAh + kb_,      szA);         \
        cpasync16(b_ + 0 * STG_T + dOff + 16, gAh + kb_ + 16, szA);         \
        cpasync16(b_ + 1 * STG_T + dOff,      gAl + kb_,      szA);         \
        cpasync16(b_ + 1 * STG_T + dOff + 16, gAl + kb_ + 16, szA);         \
        cpasync16(b_ + 2 * STG_T + dOff,      gBh + kb_,      16);          \
        cpasync16(b_ + 2 * STG_T + dOff + 16, gBh + kb_ + 16, 16);          \
        cpasync16(b_ + 3 * STG_T + dOff,      gBl + kb_,      16);          \
        cpasync16(b_ + 3 * STG_T + dOff + 16, gBl + kb_ + 16, 16);          \
    } while (0)

    // ldmatrix lane address components
    const uint32_t a_mr = (lane & 7) + ((lane >> 3) & 1) * 8;
    const uint32_t a_kc = (lane >> 4) * 8;
    const uint32_t b_nr = ((lane >> 4) & 1) * 8 + (lane & 7);
    const uint32_t b_kc = ((lane >> 3) & 1) * 8;

    const int nst = K >> 5;
    LOAD_STAGE(0, 0);
    CP_COMMIT;
    for (int s = 0; s < nst; s++) {
        if (s + 1 < nst) { LOAD_STAGE(s + 1, (s + 1) << 5); CP_COMMIT; CP_WAIT1; }
        else             { CP_WAIT0; }
        __syncthreads();

        uint32_t base = sb + (uint32_t)(s & 1) * STG_ALL;
        #pragma unroll
        for (int ksub = 0; ksub < 2; ksub++) {
            uint32_t ko = ksub * 32;
            uint32_t ah[2][4], al[2][4];
            #pragma unroll
            for (int mt = 0; mt < 2; mt++) {
                uint32_t aaddr = (uint32_t)((wm * 32 + mt * 16 + a_mr) * 80) + ko + a_kc * 2;
                LDSM4(ah[mt][0], ah[mt][1], ah[mt][2], ah[mt][3], base + 0 * STG_T + aaddr);
                LDSM4(al[mt][0], al[mt][1], al[mt][2], al[mt][3], base + 1 * STG_T + aaddr);
            }
            #pragma unroll
            for (int bg = 0; bg < 4; bg++) {
                uint32_t baddr = (uint32_t)((wn * 64 + bg * 16 + b_nr) * 80) + ko + b_kc * 2;
                uint32_t bh0, bh1, bh2, bh3, bl0, bl1, bl2, bl3;
                LDSM4(bh0, bh1, bh2, bh3, base + 2 * STG_T + baddr);
                LDSM4(bl0, bl1, bl2, bl3, base + 3 * STG_T + baddr);
                #pragma unroll
                for (int mt = 0; mt < 2; mt++) {
                    float* c0 = c[mt][bg * 2];
                    float* c1 = c[mt][bg * 2 + 1];
                    MMA16816(c0, ah[mt][0], ah[mt][1], ah[mt][2], ah[mt][3], bh0, bh1);
                    MMA16816(c0, ah[mt][0], ah[mt][1], ah[mt][2], ah[mt][3], bl0, bl1);
                    MMA16816(c0, al[mt][0], al[mt][1], al[mt][2], al[mt][3], bh0, bh1);
                    MMA16816(c1, ah[mt][0], ah[mt][1], ah[mt][2], ah[mt][3], bh2, bh3);
                    MMA16816(c1, ah[mt][0], ah[mt][1], ah[mt][2], ah[mt][3], bl2, bl3);
                    MMA16816(c1, al[mt][0], al[mt][1], al[mt][2], al[mt][3], bh2, bh3);
                }
            }
        }
        __syncthreads();
    }
#undef LOAD_STAGE

    const int rbase = bm + wm * 32 + (lane >> 2);
    const int cbase = bn + wn * 64 + (lane & 3) * 2;
    #pragma unroll
    for (int mt = 0; mt < 2; mt++) {
        #pragma unroll
        for (int nt = 0; nt < 8; nt++) {
            int rr = rbase + mt * 16;
            int cc = cbase + nt * 8;
            if (rr < M)
                *(float2*)&C[(size_t)rr * N + cc] = make_float2(c[mt][nt][0], c[mt][nt][1]);
            if (rr + 8 < M)
                *(float2*)&C[(size_t)(rr + 8) * N + cc] = make_float2(c[mt][nt][2], c[mt][nt][3]);
        }
    }
}

// ---------------- GATv2 edge logits (warp per edge) ------------------------
__global__ void k_edge_logits(const float* __restrict__ xl,
                              const float* __restrict__ xr,
                              const int* __restrict__ ei,
                              const float* __restrict__ att,
                              float* __restrict__ logits,
                              int H, int Ch)
{
    int e = (blockIdx.x * blockDim.x + threadIdx.x) >> 5;
    int lane = threadIdx.x & 31;
    if (e >= EPLUS) return;
    int s, d;
    if (e < NEDGES) { s = ei[e]; d = ei[NEDGES + e]; }
    else            { s = d = e - NEDGES; }
    const float4* pl = (const float4*)(xl + (size_t)s * HID);
    const float4* pr = (const float4*)(xr + (size_t)d * HID);
    const float4* pa = (const float4*)att;
    int Q = Ch >> 2;
    for (int h = 0; h < H; h++) {
        float sum = 0.f;
        for (int q = lane; q < Q; q += 32) {
            float4 l4 = pl[h * Q + q];
            float4 r4 = pr[h * Q + q];
            float4 a4 = pa[h * Q + q];
            float v;
            v = l4.x + r4.x; v = v > 0.f ? v : NEGSLOPE * v; sum += v * a4.x;
            v = l4.y + r4.y; v = v > 0.f ? v : NEGSLOPE * v; sum += v * a4.y;
            v = l4.z + r4.z; v = v > 0.f ? v : NEGSLOPE * v; sum += v * a4.z;
            v = l4.w + r4.w; v = v > 0.f ? v : NEGSLOPE * v; sum += v * a4.w;
        }
        #pragma unroll
        for (int o = 16; o > 0; o >>= 1)
            sum += __shfl_xor_sync(0xffffffffu, sum, o);
        if (lane == 0) logits[(size_t)e * H + h] = sum;
    }
}

// ---------------- GATv2 node aggregate, H=10 Ch=64 (warp per node,head) ----
// gather-based softmax + aggregate; fused bias + ELU + bf16 hi/lo split out
__global__ void k_gat_node64(const float* __restrict__ xl,
                             const int* __restrict__ rowptr,
                             const int* __restrict__ csr_src,
                             const int* __restrict__ csr_eid,
                             const float* __restrict__ logits,
                             const float* __restrict__ bias,
                             __nv_bfloat16* __restrict__ ohi,
                             __nv_bfloat16* __restrict__ olo)
{
    int gw = (blockIdx.x * blockDim.x + threadIdx.x) >> 5;
    int lane = threadIdx.x & 31;
    if (gw >= NNODES * HEADS) return;
    int n = gw / HEADS, h = gw - n * HEADS;
    int r0 = rowptr[n], r1 = rowptr[n + 1];

    float m = -3.4e38f;
    for (int i = r0 + lane; i < r1; i += 32)
        m = fmaxf(m, logits[(size_t)csr_eid[i] * HEADS + h]);
    #pragma unroll
    for (int o = 16; o > 0; o >>= 1)
        m = fmaxf(m, __shfl_xor_sync(0xffffffffu, m, o));

    float den = 0.f, a0 = 0.f, a1 = 0.f;
    int cbase = h * C1 + lane * 2;
    for (int i = r0; i < r1; i++) {
        int s = csr_src[i];
        float ex = expf(logits[(size_t)csr_eid[i] * HEADS + h] - m);
        den += ex;
        float2 v = *(const float2*)&xl[(size_t)s * HID + cbase];
        a0 += ex * v.x;
        a1 += ex * v.y;
    }
    float o0 = a0 / den + bias[cbase];
    float o1 = a1 / den + bias[cbase + 1];
    o0 = o0 > 0.f ? o0 : expm1f(o0);
    o1 = o1 > 0.f ? o1 : expm1f(o1);
    __nv_bfloat16 h0 = __float2bfloat16(o0), h1 = __float2bfloat16(o1);
    __nv_bfloat162 hp; hp.x = h0; hp.y = h1;
    __nv_bfloat162 lp;
    lp.x = __float2bfloat16(o0 - __bfloat162float(h0));
    lp.y = __float2bfloat16(o1 - __bfloat162float(h1));
    *(__nv_bfloat162*)&ohi[(size_t)n * HID + cbase] = hp;
    *(__nv_bfloat162*)&olo[(size_t)n * HID + cbase] = lp;
}

// ---------------- GATv2 node aggregate, H=1 Ch=640 (warp per node) ---------
__global__ void k_gat_node640(const float* __restrict__ xl,
                              const int* __restrict__ rowptr,
                              const int* __restrict__ csr_src,
                              const int* __restrict__ csr_eid,
                              const float* __restrict__ logits,
                              const float* __restrict__ bias,
                              __nv_bfloat16* __restrict__ ohi,
                              __nv_bfloat16* __restrict__ olo)
{
    int n = (blockIdx.x * blockDim.x + threadIdx.x) >> 5;
    int lane = threadIdx.x & 31;
    if (n >= NNODES) return;
    int r0 = rowptr[n], r1 = rowptr[n + 1];

    float m = -3.4e38f;
    for (int i = r0 + lane; i < r1; i += 32)
        m = fmaxf(m, logits[csr_eid[i]]);
    #pragma unroll
    for (int o = 16; o > 0; o >>= 1)
        m = fmaxf(m, __shfl_xor_sync(0xffffffffu, m, o));

    float den = 0.f;
    float acc[5][4];
    #pragma unroll
    for (int j = 0; j < 5; j++)
        #pragma unroll
        for (int q = 0; q < 4; q++) acc[j][q] = 0.f;

    for (int i = r0; i < r1; i++) {
        int s = csr_src[i];
        float ex = expf(logits[csr_eid[i]] - m);
        den += ex;
        const float4* ps = (const float4*)(xl + (size_t)s * HID);
        #pragma unroll
        for (int j = 0; j < 5; j++) {
            float4 v = ps[j * 32 + lane];
            acc[j][0] += ex * v.x;
            acc[j][1] += ex * v.y;
            acc[j][2] += ex * v.z;
            acc[j][3] += ex * v.w;
        }
    }
    float inv = 1.f / den;
    #pragma unroll
    for (int j = 0; j < 5; j++) {
        int cb = (j * 32 + lane) * 4;
        float o0 = acc[j][0] * inv + bias[cb];
        float o1 = acc[j][1] * inv + bias[cb + 1];
        float o2 = acc[j][2] * inv + bias[cb + 2];
        float o3 = acc[j][3] * inv + bias[cb + 3];
        __nv_bfloat16 h0 = __float2bfloat16(o0), h1 = __float2bfloat16(o1);
        __nv_bfloat16 h2 = __float2bfloat16(o2), h3 = __float2bfloat16(o3);
        __nv_bfloat162 hp0; hp0.x = h0; hp0.y = h1;
        __nv_bfloat162 hp1; hp1.x = h2; hp1.y = h3;
        __nv_bfloat162 lp0, lp1;
        lp0.x = __float2bfloat16(o0 - __bfloat162float(h0));
        lp0.y = __float2bfloat16(o1 - __bfloat162float(h1));
        lp1.x = __float2bfloat16(o2 - __bfloat162float(h2));
        lp1.y = __float2bfloat16(o3 - __bfloat162float(h3));
        *(__nv_bfloat162*)&ohi[(size_t)n * HID + cb]     = hp0;
        *(__nv_bfloat162*)&ohi[(size_t)n * HID + cb + 2] = hp1;
        *(__nv_bfloat162*)&olo[(size_t)n * HID + cb]     = lp0;
        *(__nv_bfloat162*)&olo[(size_t)n * HID + cb + 2] = lp1;
    }
}

// ---------------- GCN node aggregate + relu + fused pooling ----------------
__global__ void k_gcn_node(const float* __restrict__ xw,
                           const int* __restrict__ rowptr,
                           const int* __restrict__ csr_src,
                           const float* __restrict__ dinv,
                           const float* __restrict__ bg,
                           const int* __restrict__ batch,
                           int* __restrict__ gmax, float* __restrict__ gsum)
{
    int n = (blockIdx.x * blockDim.x + threadIdx.x) >> 5;
    int lane = threadIdx.x & 31;
    if (n >= NNODES) return;
    int r0 = rowptr[n], r1 = rowptr[n + 1];
    float dv = dinv[n];

    float acc[5][4];
    #pragma unroll
    for (int j = 0; j < 5; j++)
        #pragma unroll
        for (int q = 0; q < 4; q++) acc[j][q] = 0.f;

    for (int i = r0; i < r1; i++) {
        int s = csr_src[i];
        float nrm = dinv[s] * dv;
        const float4* ps = (const float4*)(xw + (size_t)s * HID);
        #pragma unroll
        for (int j = 0; j < 5; j++) {
            float4 v = ps[j * 32 + lane];
            acc[j][0] += nrm * v.x;
            acc[j][1] += nrm * v.y;
            acc[j][2] += nrm * v.z;
            acc[j][3] += nrm * v.w;
        }
    }
    int g = batch[n];
    #pragma unroll
    for (int j = 0; j < 5; j++) {
        int cb = (j * 32 + lane) * 4;
        #pragma unroll
        for (int q = 0; q < 4; q++) {
            float o = fmaxf(acc[j][q] + bg[cb + q], 0.f);
            atomicMax(&gmax[g * HID + cb + q], __float_as_int(o));
            atomicAdd(&gsum[g * HID + cb + q], o);
        }
    }
}

// ---------------- pooling tail ---------------------------------------------
__global__ void k_cnt(const int* __restrict__ batch, float* __restrict__ cnt) {
    int n = blockIdx.x * blockDim.x + threadIdx.x;
    if (n >= NNODES) return;
    atomicAdd(&cnt[batch[n]], 1.f);
}
__global__ void k_final(const int* __restrict__ gmax, const float* __restrict__ gsum,
                        const float* __restrict__ cnt, float* __restrict__ out)
{
    int idx = blockIdx.x * blockDim.x + threadIdx.x;
    if (idx >= NGRAPH * HID) return;
    int g = idx / HID, c = idx % HID;
    out[(size_t)g * (2 * HID) + c]       = __int_as_float(gmax[idx]);
    out[(size_t)g * (2 * HID) + HID + c] = gsum[idx] / fmaxf(cnt[g], 1.f);
}

// ---------------- launch ---------------------------------------------------
extern "C" void kernel_launch(void* const* d_in, const int* in_sizes, int n_in,
                              void* d_out, int out_size)
{
    const float* x     = (const float*)d_in[0];
    const int*   ei    = (const int*)d_in[1];
    const int*   batch = (const int*)d_in[2];
    const float* Wl1 = (const float*)d_in[3];
    const float* Wr1 = (const float*)d_in[4];
    const float* a1  = (const float*)d_in[5];
    const float* b1  = (const float*)d_in[6];
    const float* Wl2 = (const float*)d_in[7];
    const float* Wr2 = (const float*)d_in[8];
    const float* a2  = (const float*)d_in[9];
    const float* b2  = (const float*)d_in[10];
    const float* Wg  = (const float*)d_in[11];
    const float* bg  = (const float*)d_in[12];
    float* out = (float*)d_out;

    float *A, *B, *logits, *dinv, *gsum, *cnt;
    int *rowptr, *cntbuf, *csr_src, *csr_eid, *gmax;
    __nv_bfloat16 *xhi, *xlo, *hhi, *hlo;
    __nv_bfloat16 *w1lhi, *w1llo, *w1rhi, *w1rlo;
    __nv_bfloat16 *w2lhi, *w2llo, *w2rhi, *w2rlo, *wghi, *wglo;
    cudaGetSymbolAddress((void**)&A,       g_bufA);
    cudaGetSymbolAddress((void**)&B,       g_bufB);
    cudaGetSymbolAddress((void**)&logits,  g_logits);
    cudaGetSymbolAddress((void**)&dinv,    g_dinv);
    cudaGetSymbolAddress((void**)&rowptr,  g_rowptr);
    cudaGetSymbolAddress((void**)&cntbuf,  g_cntbuf);
    cudaGetSymbolAddress((void**)&csr_src, g_csr_src);
    cudaGetSymbolAddress((void**)&csr_eid, g_csr_eid);
    cudaGetSymbolAddress((void**)&gmax,    g_gmax);
    cudaGetSymbolAddress((void**)&gsum,    g_gsum);
    cudaGetSymbolAddress((void**)&cnt,     g_cnt);
    cudaGetSymbolAddress((void**)&xhi,     g_xhi);
    cudaGetSymbolAddress((void**)&xlo,     g_xlo);
    cudaGetSymbolAddress((void**)&hhi,     g_hhi);
    cudaGetSymbolAddress((void**)&hlo,     g_hlo);
    cudaGetSymbolAddress((void**)&w1lhi,   g_w1lhi);
    cudaGetSymbolAddress((void**)&w1llo,   g_w1llo);
    cudaGetSymbolAddress((void**)&w1rhi,   g_w1rhi);
    cudaGetSymbolAddress((void**)&w1rlo,   g_w1rlo);
    cudaGetSymbolAddress((void**)&w2lhi,   g_w2lhi);
    cudaGetSymbolAddress((void**)&w2llo,   g_w2llo);
    cudaGetSymbolAddress((void**)&w2rhi,   g_w2rhi);
    cudaGetSymbolAddress((void**)&w2rlo,   g_w2rlo);
    cudaGetSymbolAddress((void**)&wghi,    g_wghi);
    cudaGetSymbolAddress((void**)&wglo,    g_wglo);

    static bool attr_set = false;
    if (!attr_set) {
        cudaFuncSetAttribute(k_hgemm, cudaFuncAttributeMaxDynamicSharedMemorySize, 2 * STG_ALL);
        attr_set = true;
    }

    const int T = 256;
    dim3 gg(HID / 128, (NNODES + 127) / 128);            // (5, 391)
    int eb   = (EPLUS * 32 + T - 1) / T;                 // warp per edge
    int nb   = (NNODES + T - 1) / T;
    int epb  = (EPLUS + T - 1) / T;
    int ghb  = (NGRAPH * HID + T - 1) / T;
    int xsb  = (NNODES * KP1 + T - 1) / T;
    int w1b  = (HID * KP1 + T - 1) / T;
    int w2b  = (HID * HID + T - 1) / T;
    int nw64 = (NNODES * HEADS * 32 + T - 1) / T;        // warp per (node,head)
    int nwN  = (NNODES * 32 + T - 1) / T;                // warp per node

    // ---- CSR build (dst-sorted, incl self loops) ----
    k_fill_i<<<nb, T>>>(cntbuf, 0, NNODES);
    k_count<<<epb, T>>>(ei, cntbuf);
    k_scan<<<1, 1024>>>(cntbuf, rowptr);
    k_fill_i<<<nb, T>>>(cntbuf, 0, NNODES);
    k_scatter<<<epb, T>>>(ei, rowptr, cntbuf, csr_src, csr_eid);
    k_dinv<<<nb, T>>>(rowptr, dinv);

    // ---- bf16 hi/lo splits (weights + x) ----
    k_split <<<xsb, T>>>(x, xhi, xlo, NNODES, INDIM, KP1);
    k_splitT<<<w1b, T>>>(Wl1, w1lhi, w1llo, INDIM, HID, KP1);
    k_splitT<<<w1b, T>>>(Wr1, w1rhi, w1rlo, INDIM, HID, KP1);
    k_splitT<<<w2b, T>>>(Wl2, w2lhi, w2llo, HID, HID, HID);
    k_splitT<<<w2b, T>>>(Wr2, w2rhi, w2rlo, HID, HID, HID);
    k_splitT<<<w2b, T>>>(Wg,  wghi,  wglo,  HID, HID, HID);

    // ---- Layer 1: GATv2 (heads=10, C=64) ----
    k_hgemm<<<gg, T, 2 * STG_ALL>>>(xhi, xlo, w1lhi, w1llo, A, NNODES, HID, KP1);
    k_hgemm<<<gg, T, 2 * STG_ALL>>>(xhi, xlo, w1rhi, w1rlo, B, NNODES, HID, KP1);
    k_edge_logits<<<eb, T>>>(A, B, ei, a1, logits, HEADS, C1);
    k_gat_node64<<<nw64, T>>>(A, rowptr, csr_src, csr_eid, logits, b1, hhi, hlo);

    // ---- Layer 2: GATv2 (heads=1, C=640) ----
    k_hgemm<<<gg, T, 2 * STG_ALL>>>(hhi, hlo, w2lhi, w2llo, A, NNODES, HID, HID);
    k_hgemm<<<gg, T, 2 * STG_ALL>>>(hhi, hlo, w2rhi, w2rlo, B, NNODES, HID, HID);
    k_edge_logits<<<eb, T>>>(A, B, ei, a2, logits, 1, HID);
    k_gat_node640<<<nwN, T>>>(A, rowptr, csr_src, csr_eid, logits, b2, hhi, hlo);

    // ---- Layer 3: GCN + relu + fused pooling ----
    k_hgemm<<<gg, T, 2 * STG_ALL>>>(hhi, hlo, wghi, wglo, A, NNODES, HID, HID);
    k_fill_i<<<ghb, T>>>(gmax, 0, NGRAPH * HID);         // relu => values >= 0
    k_fill_f<<<ghb, T>>>(gsum, 0.f, NGRAPH * HID);
    k_fill_f<<<(NGRAPH + T - 1) / T, T>>>(cnt, 0.f, NGRAPH);
    k_cnt<<<nb, T>>>(batch, cnt);
    k_gcn_node<<<nwN, T>>>(A, rowptr, csr_src, dinv, bg, batch, gmax, gsum);
    k_final<<<ghb, T>>>(gmax, gsum, cnt, out);
}